// round 8
// baseline (speedup 1.0000x reference)
#include <cuda_runtime.h>
#include <cuda_bf16.h>
#include <cstdint>

#define H_  16
#define S_  4096
#define D_  128
#define BM  128
#define BN  64
#define NTH 256

// row strides (32-bit words): K,Q = 68 (64 data + 4 pad), V = 36 (32 data + 4 pad)
// 68 mod 32 == 4 and 36 mod 32 == 4 => fragment LDS bank = (4g+t), conflict-free.
#define SK 68
#define SQ 68
#define SV 36

// double-buffered K/V: per-buffer layout, stride 71680 bytes
#define BSTR 71680
#define KHIo 0
#define KLOo 17408
#define VHIo 34816
#define VLOo 53248
#define QHI  143360
#define QLO  178176
#define SMEM_BYTES 212992

static __device__ __forceinline__ float ex2f(float x) {
    float y; asm("ex2.approx.f32 %0, %1;" : "=f"(y) : "f"(x)); return y;
}
// split float pair (x,y) -> packed bf16x2 hi (x in low half) and residual lo
static __device__ __forceinline__ void split2(float x, float y, uint32_t& hi, uint32_t& lo) {
    asm("cvt.rn.bf16x2.f32 %0, %1, %2;" : "=r"(hi) : "f"(y), "f"(x));
    float xr = x - __uint_as_float(hi << 16);
    float yr = y - __uint_as_float(hi & 0xffff0000u);
    asm("cvt.rn.bf16x2.f32 %0, %1, %2;" : "=r"(lo) : "f"(yr), "f"(xr));
}
static __device__ __forceinline__ void split1(float x, uint16_t& h, uint16_t& l) {
    __nv_bfloat16 bh = __float2bfloat16(x);
    __nv_bfloat16 bl = __float2bfloat16(x - __bfloat162float(bh));
    h = *(uint16_t*)&bh; l = *(uint16_t*)&bl;
}
static __device__ __forceinline__ void mma16816(float* c, const uint32_t* a, uint32_t b0, uint32_t b1) {
    asm volatile("mma.sync.aligned.m16n8k16.row.col.f32.bf16.bf16.f32 "
        "{%0,%1,%2,%3}, {%4,%5,%6,%7}, {%8,%9}, {%0,%1,%2,%3};"
        : "+f"(c[0]), "+f"(c[1]), "+f"(c[2]), "+f"(c[3])
        : "r"(a[0]), "r"(a[1]), "r"(a[2]), "r"(a[3]), "r"(b0), "r"(b1));
}

__global__ __launch_bounds__(NTH, 1)
void fa_mma_split(const float* __restrict__ q, const float* __restrict__ k,
                  const float* __restrict__ v, const void* __restrict__ cu_raw,
                  float* __restrict__ out)
{
    extern __shared__ char sm[];
    __shared__ int cu_s[9];
    __shared__ int row_st[BM];

    uint32_t* Qhi = (uint32_t*)(sm + QHI);
    uint32_t* Qlo = (uint32_t*)(sm + QLO);

    const int tid  = threadIdx.x;
    const int w    = tid >> 5;
    const int lane = tid & 31;
    const int g    = lane >> 2;
    const int t    = lane & 3;

    const int m0 = (int)(gridDim.x - 1 - blockIdx.x) * BM;  // longest work first
    const int h  = blockIdx.y;

    if (tid == 0) {
        long long first8 = *(const long long*)cu_raw;  // cu[0]==0; int64 => 8 zero bytes
        if (first8 == 0) {
            const long long* c = (const long long*)cu_raw;
            #pragma unroll
            for (int i = 0; i < 9; i++) cu_s[i] = (int)c[i];
        } else {
            const int* c = (const int*)cu_raw;
            #pragma unroll
            for (int i = 0; i < 9; i++) cu_s[i] = c[i];
        }
    }
    __syncthreads();
    if (tid < BM) {
        int qpos = m0 + tid, st = 0;
        #pragma unroll
        for (int i = 1; i < 9; i++) if (cu_s[i] <= qpos) st = cu_s[i];
        row_st[tid] = st;
    }

    // ---- stage Q packed hi/lo (scaled by 1/sqrt(D)*log2(e) for base-2 softmax) ----
    const float QSC = 0.12752551286084110f;
    {
        const float4* qg = (const float4*)(q + ((size_t)h * S_ + m0) * D_);
        #pragma unroll
        for (int it = 0; it < 16; it++) {
            int idx = it * NTH + tid;
            int row = idx >> 5, c4 = idx & 31;
            float4 tq = qg[idx];
            uint32_t h01, l01, h23, l23;
            split2(tq.x * QSC, tq.y * QSC, h01, l01);
            split2(tq.z * QSC, tq.w * QSC, h23, l23);
            int wo = row * SQ + c4 * 2;
            *(uint2*)(Qhi + wo) = make_uint2(h01, h23);
            *(uint2*)(Qlo + wo) = make_uint2(l01, l23);
        }
    }

    const int wr    = m0 + w * 16;
    const int r0g   = wr + g, r1g = r0g + 8;
    __syncthreads();   // row_st visible; Q staged
    const int st0   = row_st[w * 16 + g];
    const int st1   = row_st[w * 16 + g + 8];
    const int stmin = row_st[w * 16];
    const int n_begin = (row_st[0] / BN) * BN;
    const int ntiles  = (m0 + BM - n_begin) / BN;

    const float4* kgb = (const float4*)(k + ((size_t)h * S_ + n_begin) * D_);
    const float4* vgb = (const float4*)(v + ((size_t)h * S_ + n_begin) * D_);

    float o[16][4];
    #pragma unroll
    for (int i = 0; i < 16; i++) { o[i][0]=0.f; o[i][1]=0.f; o[i][2]=0.f; o[i][3]=0.f; }
    float m0r = -1e30f, m1r = -1e30f, l0 = 0.f, l1 = 0.f;

    // ---- prologue: stage tile 0 into buffer 0 ----
    {
        #pragma unroll
        for (int it = 0; it < 8; it++) {
            int idx = it * NTH + tid;
            int row = idx >> 5, c4 = idx & 31;
            float4 tk = kgb[idx];
            uint32_t h01, l01, h23, l23;
            split2(tk.x, tk.y, h01, l01);
            split2(tk.z, tk.w, h23, l23);
            int wo = row * SK + c4 * 2;
            *(uint2*)((uint32_t*)(sm + KHIo) + wo) = make_uint2(h01, h23);
            *(uint2*)((uint32_t*)(sm + KLOo) + wo) = make_uint2(l01, l23);

            int u  = idx >> 5;
            int kv = lane + ((u & 1) << 5);
            int d0 = (u >> 1) * 4;
            float4 tv = vgb[kv * 32 + (u >> 1)];
            uint16_t hh, ll;
            uint16_t* Vhi = (uint16_t*)(sm + VHIo);
            uint16_t* Vlo = (uint16_t*)(sm + VLOo);
            split1(tv.x, hh, ll); Vhi[(d0+0)*(2*SV) + kv] = hh; Vlo[(d0+0)*(2*SV) + kv] = ll;
            split1(tv.y, hh, ll); Vhi[(d0+1)*(2*SV) + kv] = hh; Vlo[(d0+1)*(2*SV) + kv] = ll;
            split1(tv.z, hh, ll); Vhi[(d0+2)*(2*SV) + kv] = hh; Vlo[(d0+2)*(2*SV) + kv] = ll;
            split1(tv.w, hh, ll); Vhi[(d0+3)*(2*SV) + kv] = hh; Vlo[(d0+3)*(2*SV) + kv] = ll;
        }
    }
    __syncthreads();

    for (int i = 0; i < ntiles; i++) {
        const int n0   = n_begin + i * BN;
        const int cur  = i & 1;
        const int nxt  = cur ^ 1;
        const bool hasnext = (i + 1 < ntiles);
        const bool active  = !(n0 > wr + 15 || n0 + BN - 1 < stmin);

        char* bufc = sm + cur * BSTR;
        char* bufn = sm + nxt * BSTR;
        uint32_t* Khi = (uint32_t*)(bufc + KHIo);
        uint32_t* Klo = (uint32_t*)(bufc + KLOo);

        // ---- LDG K(i+1): latency overlaps QK^T compute ----
        float4 kreg[8];
        if (hasnext) {
            const float4* kg = kgb + (size_t)(i + 1) * BN * 32;
            #pragma unroll
            for (int it = 0; it < 8; it++) kreg[it] = kg[it * NTH + tid];
        }

        float s[8][4];
        if (active) {
            // ---- S = Q K^T (3 split terms) ----
            #pragma unroll
            for (int nt = 0; nt < 8; nt++) { s[nt][0]=0.f; s[nt][1]=0.f; s[nt][2]=0.f; s[nt][3]=0.f; }
            #pragma unroll
            for (int kc = 0; kc < 8; kc++) {
                uint32_t qh[4], ql[4];
                int a0 = (w*16 + g) * SQ + kc*8 + t;
                int a1 = a0 + 8*SQ;
                qh[0]=Qhi[a0]; qh[1]=Qhi[a1]; qh[2]=Qhi[a0+4]; qh[3]=Qhi[a1+4];
                ql[0]=Qlo[a0]; ql[1]=Qlo[a1]; ql[2]=Qlo[a0+4]; ql[3]=Qlo[a1+4];
                #pragma unroll
                for (int nt = 0; nt < 8; nt++) {
                    int b = (nt*8 + g) * SK + kc*8 + t;
                    uint32_t bh0 = Khi[b], bh1 = Khi[b+4];
                    uint32_t bl0 = Klo[b], bl1 = Klo[b+4];
                    mma16816(s[nt], qh, bh0, bh1);
                    mma16816(s[nt], qh, bl0, bl1);
                    mma16816(s[nt], ql, bh0, bh1);
                }
            }
        }

        // ---- STS K(i+1) -> buf nxt ----
        if (hasnext) {
            uint32_t* Khn = (uint32_t*)(bufn + KHIo);
            uint32_t* Kln = (uint32_t*)(bufn + KLOo);
            #pragma unroll
            for (int it = 0; it < 8; it++) {
                int idx = it * NTH + tid;
                int row = idx >> 5, c4 = idx & 31;
                float4 tk = kreg[it];
                uint32_t h01, l01, h23, l23;
                split2(tk.x, tk.y, h01, l01);
                split2(tk.z, tk.w, h23, l23);
                int wo = row * SK + c4 * 2;
                *(uint2*)(Khn + wo) = make_uint2(h01, h23);
                *(uint2*)(Kln + wo) = make_uint2(l01, l23);
            }
        }

        // ---- LDG V(i+1): latency overlaps softmax ----
        float4 vreg[8];
        if (hasnext) {
            const float4* vg = vgb + (size_t)(i + 1) * BN * 32;
            #pragma unroll
            for (int it = 0; it < 8; it++) {
                int u  = (it * NTH + tid) >> 5;
                int kv = lane + ((u & 1) << 5);
                vreg[it] = vg[kv * 32 + (u >> 1)];
            }
        }

        if (active) {
            // ---- mask + online softmax (base-2) ----
            float mx0 = -1e30f, mx1 = -1e30f;
            #pragma unroll
            for (int nt = 0; nt < 8; nt++) {
                int c0 = n0 + nt*8 + 2*t, c1 = c0 + 1;
                if (c0 < st0 || c0 > r0g) s[nt][0] = -1e30f;
                if (c1 < st0 || c1 > r0g) s[nt][1] = -1e30f;
                if (c0 < st1 || c0 > r1g) s[nt][2] = -1e30f;
                if (c1 < st1 || c1 > r1g) s[nt][3] = -1e30f;
                mx0 = fmaxf(mx0, fmaxf(s[nt][0], s[nt][1]));
                mx1 = fmaxf(mx1, fmaxf(s[nt][2], s[nt][3]));
            }
            mx0 = fmaxf(mx0, __shfl_xor_sync(0xffffffffu, mx0, 1));
            mx0 = fmaxf(mx0, __shfl_xor_sync(0xffffffffu, mx0, 2));
            mx1 = fmaxf(mx1, __shfl_xor_sync(0xffffffffu, mx1, 1));
            mx1 = fmaxf(mx1, __shfl_xor_sync(0xffffffffu, mx1, 2));

            float mn0 = fmaxf(m0r, mx0), mn1 = fmaxf(m1r, mx1);
            float ga0 = (mn0 > -1e29f) ? 1.f : 0.f;
            float ga1 = (mn1 > -1e29f) ? 1.f : 0.f;
            float al0 = ex2f(m0r - mn0), al1 = ex2f(m1r - mn1);
            m0r = mn0; m1r = mn1;

            uint32_t ph[8], ph2[8], pl[8], pl2[8];
            float sum0 = 0.f, sum1 = 0.f;
            #pragma unroll
            for (int nt = 0; nt < 8; nt++) {
                float p0 = ex2f(s[nt][0] - mn0) * ga0;
                float p1 = ex2f(s[nt][1] - mn0) * ga0;
                float p2 = ex2f(s[nt][2] - mn1) * ga1;
                float p3 = ex2f(s[nt][3] - mn1) * ga1;
                sum0 += p0 + p1; sum1 += p2 + p3;
                split2(p0, p1, ph[nt],  pl[nt]);
                split2(p2, p3, ph2[nt], pl2[nt]);
            }
            sum0 += __shfl_xor_sync(0xffffffffu, sum0, 1);
            sum0 += __shfl_xor_sync(0xffffffffu, sum0, 2);
            sum1 += __shfl_xor_sync(0xffffffffu, sum1, 1);
            sum1 += __shfl_xor_sync(0xffffffffu, sum1, 2);
            l0 = al0 * l0 + sum0;
            l1 = al1 * l1 + sum1;

            #pragma unroll
            for (int i2 = 0; i2 < 16; i2++) {
                o[i2][0] *= al0; o[i2][1] *= al0; o[i2][2] *= al1; o[i2][3] *= al1;
            }

            // ---- O += P Vt^T (3 split terms) ----
            const uint32_t* Vhw = (const uint32_t*)(bufc + VHIo);
            const uint32_t* Vlw = (const uint32_t*)(bufc + VLOo);
            #pragma unroll
            for (int kc = 0; kc < 4; kc++) {
                uint32_t Ah[4] = { ph[2*kc], ph2[2*kc], ph[2*kc+1], ph2[2*kc+1] };
                uint32_t Al[4] = { pl[2*kc], pl2[2*kc], pl[2*kc+1], pl2[2*kc+1] };
                #pragma unroll
                for (int ntv = 0; ntv < 16; ntv++) {
                    int b = (ntv*8 + g) * SV + kc*8 + t;
                    uint32_t bh0 = Vhw[b], bh1 = Vhw[b+4];
                    uint32_t bl0 = Vlw[b], bl1 = Vlw[b+4];
                    mma16816(o[ntv], Ah, bh0, bh1);
                    mma16816(o[ntv], Ah, bl0, bl1);
                    mma16816(o[ntv], Al, bh0, bh1);
                }
            }
        }

        // ---- STS V(i+1) -> buf nxt ----
        if (hasnext) {
            uint16_t* Vhn = (uint16_t*)(bufn + VHIo);
            uint16_t* Vln = (uint16_t*)(bufn + VLOo);
            #pragma unroll
            for (int it = 0; it < 8; it++) {
                int u  = (it * NTH + tid) >> 5;
                int kv = lane + ((u & 1) << 5);
                int d0 = (u >> 1) * 4;
                float4 tv = vreg[it];
                uint16_t hh, ll;
                split1(tv.x, hh, ll); Vhn[(d0+0)*(2*SV) + kv] = hh; Vln[(d0+0)*(2*SV) + kv] = ll;
                split1(tv.y, hh, ll); Vhn[(d0+1)*(2*SV) + kv] = hh; Vln[(d0+1)*(2*SV) + kv] = ll;
                split1(tv.z, hh, ll); Vhn[(d0+2)*(2*SV) + kv] = hh; Vln[(d0+2)*(2*SV) + kv] = ll;
                split1(tv.w, hh, ll); Vhn[(d0+3)*(2*SV) + kv] = hh; Vln[(d0+3)*(2*SV) + kv] = ll;
            }
        }
        __syncthreads();
    }

    // ---- epilogue ----
    float inv0 = 1.f / l0, inv1 = 1.f / l1;
    float* ob0 = out + ((size_t)h * S_ + r0g) * D_;
    float* ob1 = out + ((size_t)h * S_ + r1g) * D_;
    #pragma unroll
    for (int ntv = 0; ntv < 16; ntv++) {
        int d = ntv * 8 + 2 * t;
        *(float2*)(ob0 + d) = make_float2(o[ntv][0] * inv0, o[ntv][1] * inv0);
        *(float2*)(ob1 + d) = make_float2(o[ntv][2] * inv1, o[ntv][3] * inv1);
    }
}

extern "C" void kernel_launch(void* const* d_in, const int* in_sizes, int n_in,
                              void* d_out, int out_size)
{
    const float* q  = (const float*)d_in[0];
    const float* k  = (const float*)d_in[1];
    const float* v  = (const float*)d_in[2];
    const void*  cu = d_in[3];
    float* out = (float*)d_out;

    static int configured = 0;
    if (!configured) {
        cudaFuncSetAttribute(fa_mma_split,
                             cudaFuncAttributeMaxDynamicSharedMemorySize, SMEM_BYTES);
        configured = 1;
    }
    dim3 grid(S_ / BM, H_);
    fa_mma_split<<<grid, NTH, SMEM_BYTES>>>(q, k, v, cu, out);
}

// round 9
// speedup vs baseline: 1.1906x; 1.1906x over previous
#include <cuda_runtime.h>
#include <cuda_bf16.h>
#include <cstdint>

#define H_  16
#define S_  4096
#define D_  128
#define BM  128
#define BN  64
#define NTH 256

// row strides (32-bit words): K,Q = 68 (64 data + 4 pad), V = 36 (32 data + 4 pad)
// byte strides 272 / 144: both ≡ 16 (mod 128) => ldmatrix phases hit all 32 banks.
#define SK 68
#define SQ 68
#define SV 36

// smem byte offsets
#define KHI 0
#define KLO 17408
#define VHI 34816
#define VLO 53248
#define QHI 71680
#define QLO 106496
#define SMEM_BYTES 141312

static __device__ __forceinline__ uint32_t smem_u32(const void* p) {
    uint32_t a;
    asm("{ .reg .u64 t; cvta.to.shared.u64 t, %1; cvt.u32.u64 %0, t; }" : "=r"(a) : "l"(p));
    return a;
}
static __device__ __forceinline__ float ex2f(float x) {
    float y; asm("ex2.approx.f32 %0, %1;" : "=f"(y) : "f"(x)); return y;
}
// split float pair (x,y) -> packed bf16x2 hi (x in low half) and residual lo
static __device__ __forceinline__ void split2(float x, float y, uint32_t& hi, uint32_t& lo) {
    asm("cvt.rn.bf16x2.f32 %0, %1, %2;" : "=r"(hi) : "f"(y), "f"(x));
    float xr = x - __uint_as_float(hi << 16);
    float yr = y - __uint_as_float(hi & 0xffff0000u);
    asm("cvt.rn.bf16x2.f32 %0, %1, %2;" : "=r"(lo) : "f"(yr), "f"(xr));
}
static __device__ __forceinline__ void split1(float x, uint16_t& h, uint16_t& l) {
    __nv_bfloat16 bh = __float2bfloat16(x);
    __nv_bfloat16 bl = __float2bfloat16(x - __bfloat162float(bh));
    h = *(uint16_t*)&bh; l = *(uint16_t*)&bl;
}
static __device__ __forceinline__ void mma16816(float* c, const uint32_t* a, uint32_t b0, uint32_t b1) {
    asm volatile("mma.sync.aligned.m16n8k16.row.col.f32.bf16.bf16.f32 "
        "{%0,%1,%2,%3}, {%4,%5,%6,%7}, {%8,%9}, {%0,%1,%2,%3};"
        : "+f"(c[0]), "+f"(c[1]), "+f"(c[2]), "+f"(c[3])
        : "r"(a[0]), "r"(a[1]), "r"(a[2]), "r"(a[3]), "r"(b0), "r"(b1));
}
#define LDSM4(r0,r1,r2,r3,a) \
    asm volatile("ldmatrix.sync.aligned.m8n8.x4.shared.b16 {%0,%1,%2,%3}, [%4];" \
        : "=r"(r0),"=r"(r1),"=r"(r2),"=r"(r3) : "r"(a))

__global__ __launch_bounds__(NTH, 1)
void fa_mma_split(const float* __restrict__ q, const float* __restrict__ k,
                  const float* __restrict__ v, const void* __restrict__ cu_raw,
                  float* __restrict__ out)
{
    extern __shared__ char sm[];
    __shared__ int cu_s[9];
    __shared__ int row_st[BM];

    uint32_t* Khi = (uint32_t*)(sm + KHI);
    uint32_t* Klo = (uint32_t*)(sm + KLO);
    uint16_t* Vhi = (uint16_t*)(sm + VHI);
    uint16_t* Vlo = (uint16_t*)(sm + VLO);
    uint32_t* Qhi = (uint32_t*)(sm + QHI);
    uint32_t* Qlo = (uint32_t*)(sm + QLO);

    const int tid  = threadIdx.x;
    const int w    = tid >> 5;
    const int lane = tid & 31;
    const int g    = lane >> 2;
    const int t    = lane & 3;

    const int m0 = (int)(gridDim.x - 1 - blockIdx.x) * BM;  // longest work first
    const int h  = blockIdx.y;

    if (tid == 0) {
        long long first8 = *(const long long*)cu_raw;  // cu[0]==0; int64 => 8 zero bytes
        if (first8 == 0) {
            const long long* c = (const long long*)cu_raw;
            #pragma unroll
            for (int i = 0; i < 9; i++) cu_s[i] = (int)c[i];
        } else {
            const int* c = (const int*)cu_raw;
            #pragma unroll
            for (int i = 0; i < 9; i++) cu_s[i] = c[i];
        }
    }
    __syncthreads();
    if (tid < BM) {
        int qpos = m0 + tid, st = 0;
        #pragma unroll
        for (int i = 1; i < 9; i++) if (cu_s[i] <= qpos) st = cu_s[i];
        row_st[tid] = st;
    }

    // ---- stage Q packed hi/lo (scaled by 1/sqrt(D)*log2(e) for base-2 softmax) ----
    const float QSC = 0.12752551286084110f;
    {
        const float4* qg = (const float4*)(q + ((size_t)h * S_ + m0) * D_);
        #pragma unroll
        for (int it = 0; it < 16; it++) {
            int idx = it * NTH + tid;
            int row = idx >> 5, c4 = idx & 31;
            float4 tq = qg[idx];
            uint32_t h01, l01, h23, l23;
            split2(tq.x * QSC, tq.y * QSC, h01, l01);
            split2(tq.z * QSC, tq.w * QSC, h23, l23);
            int wo = row * SQ + c4 * 2;
            *(uint2*)(Qhi + wo) = make_uint2(h01, h23);
            *(uint2*)(Qlo + wo) = make_uint2(l01, l23);
        }
    }
    __syncthreads();   // row_st visible to all warps; Q staged

    const int wr    = m0 + w * 16;
    const int r0g   = wr + g, r1g = r0g + 8;
    const int st0   = row_st[w * 16 + g];
    const int st1   = row_st[w * 16 + g + 8];
    const int stmin = row_st[w * 16];
    const int n_begin = (row_st[0] / BN) * BN;
    const int n_end   = m0 + BM;

    // ---- ldmatrix per-lane base addresses ----
    const uint32_t smb = smem_u32(sm);
    const uint32_t qaA = smb + QHI + (uint32_t)((w*16 + (lane & 15)) * 272 + ((lane >> 4) << 4));
    const uint32_t qlA = qaA + (QLO - QHI);
    const uint32_t kbA = smb + KHI + (uint32_t)((((lane & 7) + ((lane >> 4) << 3)) * 272) + (((lane >> 3) & 1) << 4));
    const uint32_t klA = kbA + (KLO - KHI);
    const uint32_t vbA = smb + VHI + (uint32_t)((((lane & 7) + ((lane >> 4) << 3)) * 144) + (((lane >> 3) & 1) << 4));
    const uint32_t vlA = vbA + (VLO - VHI);

    float o[16][4];
    #pragma unroll
    for (int i = 0; i < 16; i++) { o[i][0]=0.f; o[i][1]=0.f; o[i][2]=0.f; o[i][3]=0.f; }
    float m0r = -1e30f, m1r = -1e30f, l0 = 0.f, l1 = 0.f;

    for (int n0 = n_begin; n0 < n_end; n0 += BN) {
        // ---- LDG K/V tile into registers BEFORE the barrier (overlaps barrier wait) ----
        float4 kreg[8], vreg[8];
        {
            const float4* kg = (const float4*)(k + ((size_t)h * S_ + n0) * D_);
            const float4* vg = (const float4*)(v + ((size_t)h * S_ + n0) * D_);
            #pragma unroll
            for (int it = 0; it < 8; it++) {
                kreg[it] = kg[it * NTH + tid];
                int u  = (it * NTH + tid) >> 5;
                int kv = lane + ((u & 1) << 5);
                vreg[it] = vg[kv * 32 + (u >> 1)];
            }
        }
        __syncthreads();   // prev tile's compute done; safe to overwrite K/V smem

        // ---- STS: K packed hi/lo + V transposed halves (conflict-free) ----
        #pragma unroll
        for (int it = 0; it < 8; it++) {
            int idx = it * NTH + tid;
            int row = idx >> 5, c4 = idx & 31;
            float4 tk = kreg[it];
            uint32_t h01, l01, h23, l23;
            split2(tk.x, tk.y, h01, l01);
            split2(tk.z, tk.w, h23, l23);
            int wo = row * SK + c4 * 2;
            *(uint2*)(Khi + wo) = make_uint2(h01, h23);
            *(uint2*)(Klo + wo) = make_uint2(l01, l23);

            int u  = idx >> 5;
            int kv = lane + ((u & 1) << 5);
            int d0 = (u >> 1) * 4;
            float4 tv = vreg[it];
            uint16_t hh, ll;
            split1(tv.x, hh, ll); Vhi[(d0+0)*(2*SV) + kv] = hh; Vlo[(d0+0)*(2*SV) + kv] = ll;
            split1(tv.y, hh, ll); Vhi[(d0+1)*(2*SV) + kv] = hh; Vlo[(d0+1)*(2*SV) + kv] = ll;
            split1(tv.z, hh, ll); Vhi[(d0+2)*(2*SV) + kv] = hh; Vlo[(d0+2)*(2*SV) + kv] = ll;
            split1(tv.w, hh, ll); Vhi[(d0+3)*(2*SV) + kv] = hh; Vlo[(d0+3)*(2*SV) + kv] = ll;
        }
        __syncthreads();

        if (!(n0 > wr + 15 || n0 + BN - 1 < stmin)) {
            // ---- S = Q K^T (3 split terms, ldmatrix fragments) ----
            float s[8][4];
            #pragma unroll
            for (int nt = 0; nt < 8; nt++) { s[nt][0]=0.f; s[nt][1]=0.f; s[nt][2]=0.f; s[nt][3]=0.f; }
            #pragma unroll
            for (int kc = 0; kc < 8; kc++) {
                uint32_t qh[4], ql[4];
                LDSM4(qh[0], qh[1], qh[2], qh[3], qaA + kc * 32);
                LDSM4(ql[0], ql[1], ql[2], ql[3], qlA + kc * 32);
                #pragma unroll
                for (int p = 0; p < 4; p++) {
                    uint32_t bh[4], bl[4];
                    LDSM4(bh[0], bh[1], bh[2], bh[3], kbA + p * 4352 + kc * 32);
                    LDSM4(bl[0], bl[1], bl[2], bl[3], klA + p * 4352 + kc * 32);
                    mma16816(s[2*p],   qh, bh[0], bh[1]);
                    mma16816(s[2*p],   qh, bl[0], bl[1]);
                    mma16816(s[2*p],   ql, bh[0], bh[1]);
                    mma16816(s[2*p+1], qh, bh[2], bh[3]);
                    mma16816(s[2*p+1], qh, bl[2], bl[3]);
                    mma16816(s[2*p+1], ql, bh[2], bh[3]);
                }
            }

            // ---- mask + online softmax (base-2) ----
            float mx0 = -1e30f, mx1 = -1e30f;
            #pragma unroll
            for (int nt = 0; nt < 8; nt++) {
                int c0 = n0 + nt*8 + 2*t, c1 = c0 + 1;
                if (c0 < st0 || c0 > r0g) s[nt][0] = -1e30f;
                if (c1 < st0 || c1 > r0g) s[nt][1] = -1e30f;
                if (c0 < st1 || c0 > r1g) s[nt][2] = -1e30f;
                if (c1 < st1 || c1 > r1g) s[nt][3] = -1e30f;
                mx0 = fmaxf(mx0, fmaxf(s[nt][0], s[nt][1]));
                mx1 = fmaxf(mx1, fmaxf(s[nt][2], s[nt][3]));
            }
            mx0 = fmaxf(mx0, __shfl_xor_sync(0xffffffffu, mx0, 1));
            mx0 = fmaxf(mx0, __shfl_xor_sync(0xffffffffu, mx0, 2));
            mx1 = fmaxf(mx1, __shfl_xor_sync(0xffffffffu, mx1, 1));
            mx1 = fmaxf(mx1, __shfl_xor_sync(0xffffffffu, mx1, 2));

            float mn0 = fmaxf(m0r, mx0), mn1 = fmaxf(m1r, mx1);
            float ga0 = (mn0 > -1e29f) ? 1.f : 0.f;
            float ga1 = (mn1 > -1e29f) ? 1.f : 0.f;
            float al0 = ex2f(m0r - mn0), al1 = ex2f(m1r - mn1);
            m0r = mn0; m1r = mn1;

            uint32_t ph[8], ph2[8], pl[8], pl2[8];
            float sum0 = 0.f, sum1 = 0.f;
            #pragma unroll
            for (int nt = 0; nt < 8; nt++) {
                float p0 = ex2f(s[nt][0] - mn0) * ga0;
                float p1 = ex2f(s[nt][1] - mn0) * ga0;
                float p2 = ex2f(s[nt][2] - mn1) * ga1;
                float p3 = ex2f(s[nt][3] - mn1) * ga1;
                sum0 += p0 + p1; sum1 += p2 + p3;
                split2(p0, p1, ph[nt],  pl[nt]);
                split2(p2, p3, ph2[nt], pl2[nt]);
            }
            sum0 += __shfl_xor_sync(0xffffffffu, sum0, 1);
            sum0 += __shfl_xor_sync(0xffffffffu, sum0, 2);
            sum1 += __shfl_xor_sync(0xffffffffu, sum1, 1);
            sum1 += __shfl_xor_sync(0xffffffffu, sum1, 2);
            l0 = al0 * l0 + sum0;
            l1 = al1 * l1 + sum1;

            #pragma unroll
            for (int i = 0; i < 16; i++) {
                o[i][0] *= al0; o[i][1] *= al0; o[i][2] *= al1; o[i][3] *= al1;
            }

            // ---- O += P Vt^T (3 split terms, ldmatrix fragments) ----
            #pragma unroll
            for (int kc = 0; kc < 4; kc++) {
                uint32_t Ah[4] = { ph[2*kc], ph2[2*kc], ph[2*kc+1], ph2[2*kc+1] };
                uint32_t Al[4] = { pl[2*kc], pl2[2*kc], pl[2*kc+1], pl2[2*kc+1] };
                #pragma unroll
                for (int p = 0; p < 8; p++) {
                    uint32_t bh[4], bl[4];
                    LDSM4(bh[0], bh[1], bh[2], bh[3], vbA + p * 2304 + kc * 32);
                    LDSM4(bl[0], bl[1], bl[2], bl[3], vlA + p * 2304 + kc * 32);
                    mma16816(o[2*p],   Ah, bh[0], bh[1]);
                    mma16816(o[2*p],   Ah, bl[0], bl[1]);
                    mma16816(o[2*p],   Al, bh[0], bh[1]);
                    mma16816(o[2*p+1], Ah, bh[2], bh[3]);
                    mma16816(o[2*p+1], Ah, bl[2], bl[3]);
                    mma16816(o[2*p+1], Al, bh[2], bh[3]);
                }
            }
        }
    }

    // ---- epilogue ----
    float inv0 = 1.f / l0, inv1 = 1.f / l1;
    float* ob0 = out + ((size_t)h * S_ + r0g) * D_;
    float* ob1 = out + ((size_t)h * S_ + r1g) * D_;
    #pragma unroll
    for (int ntv = 0; ntv < 16; ntv++) {
        int d = ntv * 8 + 2 * t;
        *(float2*)(ob0 + d) = make_float2(o[ntv][0] * inv0, o[ntv][1] * inv0);
        *(float2*)(ob1 + d) = make_float2(o[ntv][2] * inv1, o[ntv][3] * inv1);
    }
}

extern "C" void kernel_launch(void* const* d_in, const int* in_sizes, int n_in,
                              void* d_out, int out_size)
{
    const float* q  = (const float*)d_in[0];
    const float* k  = (const float*)d_in[1];
    const float* v  = (const float*)d_in[2];
    const void*  cu = d_in[3];
    float* out = (float*)d_out;

    static int configured = 0;
    if (!configured) {
        cudaFuncSetAttribute(fa_mma_split,
                             cudaFuncAttributeMaxDynamicSharedMemorySize, SMEM_BYTES);
        configured = 1;
    }
    dim3 grid(S_ / BM, H_);
    fa_mma_split<<<grid, NTH, SMEM_BYTES>>>(q, k, v, cu, out);
}